// round 15
// baseline (speedup 1.0000x reference)
#include <cuda_runtime.h>
#include <cuda_fp16.h>
#include <cstdint>

#define NB 8
#define NT 1024
#define ND 1024
#define NH 16
#define HD 64
// hd^-0.5 * log2(e), folded into Q projection output (exp2-domain softmax)
#define QSCALE 0.1803368801111243f

// ---------------- scratch (device globals; no allocation allowed) ----------
__device__ __half g_xh[NB * NT * ND];
__device__ __half g_wqh[ND * ND], g_wkh[ND * ND], g_wvh[ND * ND], g_woh[ND * ND];
__device__ __half g_q[NB * NH * NT * HD], g_k[NB * NH * NT * HD];
__device__ __half g_vt[NB * NH * HD * NT];         // [b,h,d,t]
__device__ __half g_oh[NB * NT * ND];

// ---------------- helpers ---------------------------------------------------
__device__ __forceinline__ uint32_t smem_to_u32(const void* p) {
    uint32_t a;
    asm("{ .reg .u64 t; cvta.to.shared.u64 t, %1; cvt.u32.u64 %0, t; }"
        : "=r"(a) : "l"(p));
    return a;
}
__device__ __forceinline__ void ldsm4(uint32_t* r, uint32_t addr) {
    asm volatile("ldmatrix.sync.aligned.m8n8.x4.shared.b16 {%0,%1,%2,%3}, [%4];"
                 : "=r"(r[0]), "=r"(r[1]), "=r"(r[2]), "=r"(r[3]) : "r"(addr));
}
__device__ __forceinline__ void mma_f16(float* d, const uint32_t* a,
                                        uint32_t b0, uint32_t b1) {
    asm volatile(
        "mma.sync.aligned.m16n8k16.row.col.f32.f16.f16.f32 "
        "{%0,%1,%2,%3}, {%4,%5,%6,%7}, {%8,%9}, {%0,%1,%2,%3};"
        : "+f"(d[0]), "+f"(d[1]), "+f"(d[2]), "+f"(d[3])
        : "r"(a[0]), "r"(a[1]), "r"(a[2]), "r"(a[3]), "r"(b0), "r"(b1));
}
__device__ __forceinline__ void cpa16(uint32_t dst, const void* gsrc) {
    asm volatile("cp.async.cg.shared.global [%0], [%1], 16;"
                 :: "r"(dst), "l"(__cvta_generic_to_global(gsrc)) : "memory");
}
__device__ __forceinline__ uint32_t sw128(uint32_t off) {
    return off ^ ((off >> 3) & 0x70);
}
__device__ __forceinline__ uint32_t pack2h(float a, float b) {
    __half2 h = __floats2half2_rn(a, b);
    return *reinterpret_cast<uint32_t*>(&h);
}
__device__ __forceinline__ float ex2(float x) {
    float r;
    asm("ex2.approx.f32 %0, %1;" : "=f"(r) : "f"(x));
    return r;
}

// ---------------- fp32 -> fp16 conversion ------------------------------------
__global__ __launch_bounds__(256) void toh_kernel(
    const float* __restrict__ src, __half* __restrict__ dst, int n4)
{
    int i = blockIdx.x * 256 + threadIdx.x;
    if (i >= n4) return;
    float4 v = ((const float4*)src)[i];
    uint2 o;
    o.x = pack2h(v.x, v.y);
    o.y = pack2h(v.z, v.w);
    ((uint2*)dst)[i] = o;
}
// all 4 weight matrices in one launch; per-weight n4 = 2^18
__global__ __launch_bounds__(256) void toh4_kernel(
    const float* __restrict__ s0, const float* __restrict__ s1,
    const float* __restrict__ s2, const float* __restrict__ s3,
    __half* __restrict__ d0, __half* __restrict__ d1,
    __half* __restrict__ d2, __half* __restrict__ d3)
{
    const int i = blockIdx.x * 256 + threadIdx.x;
    const int w = i >> 18;
    const int j = i & 0x3FFFF;
    const float* src = (w == 0) ? s0 : (w == 1) ? s1 : (w == 2) ? s2 : s3;
    __half* dst = (w == 0) ? d0 : (w == 1) ? d1 : (w == 2) ? d2 : d3;
    float4 v = ((const float4*)src)[j];
    uint2 o;
    o.x = pack2h(v.x, v.y);
    o.y = pack2h(v.z, v.w);
    ((uint2*)dst)[j] = o;
}

// ---------------- fp16 single-pass GEMM, 4-stage pipeline --------------------
// C[m,n] = sum_k A[m,k]*W[n,k]; CTA 256x128, 8 warps (4m x 2n), warp 64x64,
// k-step 16, 4-stage cp.async pipeline (load issued 3 iters ahead).
// Rows padded to 48B. smem: 4 x 18432 = 73728 B.
// MODE 0: output GEMM -> fp32 [M,ND] + bias_o.
// MODE 1: fused QKV over N=3072; region 0=Q(bias+QSCALE), 1=K, 2=V([b,h,d,t]).
template <int MODE>
__global__ __launch_bounds__(256, 1) void gemm_f16(
    const __half* __restrict__ A,
    const __half* __restrict__ W0, const __half* __restrict__ W1,
    const __half* __restrict__ W2,
    const float* __restrict__ bias_q, const float* __restrict__ bias_v,
    const float* __restrict__ bias_o, float* __restrict__ Cf,
    __half* __restrict__ Qo, __half* __restrict__ Ko, __half* __restrict__ Vt)
{
    extern __shared__ __align__(16) char smemc[];
    const uint32_t sb = smem_to_u32(smemc);
    const int tid = threadIdx.x;
    const int wid = tid >> 5;
    const int lane = tid & 31;
    const int g = lane >> 2;
    const int t = lane & 3;
    const int m0 = (wid >> 1) * 64;
    const int n0 = (wid & 1) * 64;
    const int brow = blockIdx.y * 256;
    const int bcol = blockIdx.x * 128;

    int region = 0;
    const __half* B = W0;
    if (MODE == 1) {
        region = bcol >> 10;
        B = (region == 0) ? W0 : (region == 1 ? W1 : W2);
    }
    const int bn = bcol & 1023;

    float acc[4][8][4];
#pragma unroll
    for (int i = 0; i < 4; i++)
#pragma unroll
        for (int j = 0; j < 8; j++)
#pragma unroll
            for (int r = 0; r < 4; r++) acc[i][j][r] = 0.0f;

    auto load_stage = [&](int s, int kt) {
#pragma unroll
        for (int i = 0; i < 3; i++) {
            const int c = i * 256 + tid;          // 768 chunks of 16B
            uint32_t dst;
            const __half* src;
            if (c < 512) {                        // A: 256 rows x 2 chunks
                const int row = c >> 1, ch = c & 1;
                dst = sb + s * 18432 + row * 48 + ch * 16;
                src = A + (size_t)(brow + row) * ND + kt * 16 + ch * 8;
            } else {                              // B: 128 rows x 2 chunks
                const int w = c - 512;
                const int row = w >> 1, ch = w & 1;
                dst = sb + s * 18432 + 12288 + row * 48 + ch * 16;
                src = B + (size_t)(bn + row) * ND + kt * 16 + ch * 8;
            }
            cpa16(dst, src);
        }
        asm volatile("cp.async.commit_group;" ::: "memory");
    };

    load_stage(0, 0);
    load_stage(1, 1);
    load_stage(2, 2);

    const uint32_t a_row = lane & 15;
    const uint32_t a_coff = (lane >> 4) << 4;
    const uint32_t b_row = (lane & 7) + (((lane >> 4) & 1) << 3);
    const uint32_t b_coff = ((lane >> 3) & 1) << 4;

    for (int kt = 0; kt < 64; kt++) {
        const int s = kt & 3;
        if (kt + 3 < 64) {
            load_stage((kt + 3) & 3, kt + 3);     // stage freed at end of kt-1
            asm volatile("cp.async.wait_group 3;" ::: "memory");
        } else if (kt == 61) {
            asm volatile("cp.async.wait_group 2;" ::: "memory");
        } else if (kt == 62) {
            asm volatile("cp.async.wait_group 1;" ::: "memory");
        } else {
            asm volatile("cp.async.wait_group 0;" ::: "memory");
        }
        __syncthreads();

        const uint32_t base = sb + s * 18432;
        uint32_t a[4][4], b[4][4];
#pragma unroll
        for (int mi = 0; mi < 4; mi++)
            ldsm4(a[mi], base + (m0 + 16 * mi + a_row) * 48 + a_coff);
#pragma unroll
        for (int nj = 0; nj < 4; nj++)
            ldsm4(b[nj], base + 12288 + (n0 + 16 * nj + b_row) * 48 + b_coff);
#pragma unroll
        for (int mi = 0; mi < 4; mi++)
#pragma unroll
            for (int oct = 0; oct < 8; oct++) {
                const int j = oct >> 1, r = (oct & 1) * 2;
                mma_f16(acc[mi][oct], a[mi], b[j][r], b[j][r + 1]);
            }
        __syncthreads();
    }

#pragma unroll
    for (int mi = 0; mi < 4; mi++) {
#pragma unroll
        for (int oct = 0; oct < 8; oct++) {
            const int mA = brow + m0 + 16 * mi + g;   // mA+8 stays in-batch
            const int c = n0 + 8 * oct + 2 * t;
            float2 v0, v1;
            v0.x = acc[mi][oct][0]; v0.y = acc[mi][oct][1];
            v1.x = acc[mi][oct][2]; v1.y = acc[mi][oct][3];
            if (MODE == 0) {
                const int n = bcol + c;
                const float2 bv = *(const float2*)(bias_o + n);
                v0.x += bv.x; v0.y += bv.y;
                v1.x += bv.x; v1.y += bv.y;
                *(float2*)&Cf[(size_t)mA * ND + n] = v0;
                *(float2*)&Cf[(size_t)(mA + 8) * ND + n] = v1;
            } else {
                const int nn = bn + c;
                const int hh = nn >> 6, d = nn & 63;
                const int b0_ = mA >> 10, t0 = mA & 1023;
                if (region == 0) {
                    const float2 bv = *(const float2*)(bias_q + nn);
                    v0.x = (v0.x + bv.x) * QSCALE; v0.y = (v0.y + bv.y) * QSCALE;
                    v1.x = (v1.x + bv.x) * QSCALE; v1.y = (v1.y + bv.y) * QSCALE;
                    const size_t i0 = (((size_t)(b0_ * NH + hh) * NT + t0) << 6) + d;
                    *(uint32_t*)&Qo[i0] = pack2h(v0.x, v0.y);
                    *(uint32_t*)&Qo[i0 + (8 << 6)] = pack2h(v1.x, v1.y);
                } else if (region == 1) {
                    const size_t i0 = (((size_t)(b0_ * NH + hh) * NT + t0) << 6) + d;
                    *(uint32_t*)&Ko[i0] = pack2h(v0.x, v0.y);
                    *(uint32_t*)&Ko[i0 + (8 << 6)] = pack2h(v1.x, v1.y);
                } else {
                    const float2 bv = *(const float2*)(bias_v + nn);
                    v0.x += bv.x; v0.y += bv.y;
                    v1.x += bv.x; v1.y += bv.y;
                    const size_t vbase = ((size_t)(b0_ * NH + hh) * HD + d) * NT;
                    Vt[vbase + t0] = __float2half_rn(v0.x);
                    Vt[vbase + NT + t0] = __float2half_rn(v0.y);
                    Vt[vbase + t0 + 8] = __float2half_rn(v1.x);
                    Vt[vbase + NT + t0 + 8] = __float2half_rn(v1.y);
                }
            }
        }
    }
}

// ---------------- fp16 causal flash attention --------------------------------
// Block: 256 queries x one (b,h); 8 warps x 32 q rows. Q frags persistent in
// registers; K/V in 64-key sw128 tiles, double-buffered; fully masked diagonal
// tiles skipped per warp; O-rescale executed only when the running max grows.
// smem: Q [0,32768); stage s: K @32768+s*16384, V @+8192. Total 65536 B.
__global__ __launch_bounds__(256, 1) void attn_f16(
    const __half* __restrict__ Q, const __half* __restrict__ K,
    const __half* __restrict__ Vt, __half* __restrict__ O)
{
    extern __shared__ __align__(16) char smemc[];
    const uint32_t sb = smem_to_u32(smemc);
    const int qt = gridDim.x - 1 - blockIdx.x;   // heavy blocks first
    const int bh = blockIdx.y;
    const int tid = threadIdx.x;
    const int wid = tid >> 5;
    const int lane = tid & 31;
    const int g = lane >> 2;
    const int t = lane & 3;

    const size_t off = (size_t)bh * NT * HD;     // same count for Vt [b,h,d,t]

    auto load_tile = [&](int kt, int s) {
        const uint32_t kb = sb + 32768 + s * 16384;
        const uint32_t vb = kb + 8192;
#pragma unroll
        for (int i = 0; i < 4; i++) {
            const int c = i * 256 + tid;          // 1024 chunks
            const int tile = c >> 9;              // 0:K 1:V
            const int w = c & 511;
            const int row = w >> 3;
            const int ch = w & 7;
            if (tile == 0)
                cpa16(kb + sw128(row * 128 + ch * 16),
                      K + off + (size_t)(kt * 64 + row) * HD + ch * 8);
            else
                cpa16(vb + sw128(row * 128 + ch * 16),
                      Vt + off + (size_t)row * NT + kt * 64 + ch * 8);
        }
        asm volatile("cp.async.commit_group;" ::: "memory");
    };

    // stage Q (256 x 64 halves): 2048 chunks
#pragma unroll
    for (int i = 0; i < 8; i++) {
        const int c = i * 256 + tid;
        const int row = c >> 3;
        const int ch = c & 7;
        cpa16(sb + sw128(row * 128 + ch * 16),
              Q + off + (size_t)(qt * 256 + row) * HD + ch * 8);
    }
    asm volatile("cp.async.commit_group;" ::: "memory");

    const int nkt = 4 * qt + 4;
    load_tile(0, 0);
    asm volatile("cp.async.wait_group 1;" ::: "memory");   // Q staged
    __syncthreads();

    const uint32_t a_row = lane & 15;
    const uint32_t a_coff = (lane >> 4) << 4;
    const uint32_t b_row = (lane & 7) + (((lane >> 4) & 1) << 3);
    const uint32_t b_coff = ((lane >> 3) & 1) << 4;

    // persistent Q fragments: 2 m-tiles x 4 k-chunks
    uint32_t qf[2][4][4];
#pragma unroll
    for (int mi = 0; mi < 2; mi++)
#pragma unroll
        for (int kc = 0; kc < 4; kc++)
            ldsm4(qf[mi][kc],
                  sb + sw128((32 * wid + 16 * mi + a_row) * 128 + kc * 32 + a_coff));

    float Oa[2][8][4];
#pragma unroll
    for (int mi = 0; mi < 2; mi++)
#pragma unroll
        for (int j = 0; j < 8; j++)
#pragma unroll
            for (int r = 0; r < 4; r++) Oa[mi][j][r] = 0.0f;
    float mrow[2][2] = {{-3.0e38f, -3.0e38f}, {-3.0e38f, -3.0e38f}};
    float lrow[2][2] = {{0.0f, 0.0f}, {0.0f, 0.0f}};

    for (int kt = 0; kt < nkt; kt++) {
        const int s = kt & 1;
        if (kt + 1 < nkt) {
            load_tile(kt + 1, s ^ 1);
            asm volatile("cp.async.wait_group 1;" ::: "memory");
        } else {
            asm volatile("cp.async.wait_group 0;" ::: "memory");
        }
        __syncthreads();

        if (kt * 64 <= qt * 256 + 32 * wid + 31) {   // warp-uniform causal skip
            const uint32_t kb = sb + 32768 + s * 16384;
            const uint32_t vb = kb + 8192;

            // ---- S = Q K^T ----
            float S[2][8][4];
#pragma unroll
            for (int mi = 0; mi < 2; mi++)
#pragma unroll
                for (int j = 0; j < 8; j++)
#pragma unroll
                    for (int r = 0; r < 4; r++) S[mi][j][r] = 0.0f;

#pragma unroll
            for (int kc = 0; kc < 4; kc++) {
                uint32_t bK[4][4];
#pragma unroll
                for (int nj = 0; nj < 4; nj++)
                    ldsm4(bK[nj],
                          kb + sw128((16 * nj + b_row) * 128 + kc * 32 + b_coff));
#pragma unroll
                for (int oct = 0; oct < 8; oct++) {
                    const int j = oct >> 1, r = (oct & 1) * 2;
                    mma_f16(S[0][oct], qf[0][kc], bK[j][r], bK[j][r + 1]);
                    mma_f16(S[1][oct], qf[1][kc], bK[j][r], bK[j][r + 1]);
                }
            }

            // ---- causal mask (diagonal region only) ----
            if (kt >= 4 * qt) {
#pragma unroll
                for (int mi = 0; mi < 2; mi++)
#pragma unroll
                    for (int j = 0; j < 8; j++)
#pragma unroll
                        for (int r = 0; r < 4; r++) {
                            const int rq = qt * 256 + 32 * wid + 16 * mi + g
                                         + 8 * (r >> 1);
                            const int ck = kt * 64 + 8 * j + 2 * t + (r & 1);
                            if (ck > rq) S[mi][j][r] = -1.0e30f;
                        }
            }

            // ---- online softmax (exp2 domain, conditional rescale) ----
#pragma unroll
            for (int mi = 0; mi < 2; mi++)
#pragma unroll
                for (int gg = 0; gg < 2; gg++) {
                    float mx = -3.0e38f;
#pragma unroll
                    for (int j = 0; j < 8; j++) {
                        mx = fmaxf(mx, S[mi][j][gg * 2]);
                        mx = fmaxf(mx, S[mi][j][gg * 2 + 1]);
                    }
                    mx = fmaxf(mx, __shfl_xor_sync(0xffffffffu, mx, 1));
                    mx = fmaxf(mx, __shfl_xor_sync(0xffffffffu, mx, 2));
                    if (mx > mrow[mi][gg]) {       // rescale only when max grows
                        const float corr = ex2(mrow[mi][gg] - mx);
                        mrow[mi][gg] = mx;
                        lrow[mi][gg] *= corr;
#pragma unroll
                        for (int j = 0; j < 8; j++) {
                            Oa[mi][j][gg * 2] *= corr;
                            Oa[mi][j][gg * 2 + 1] *= corr;
                        }
                    }
                    const float mcur = mrow[mi][gg];
                    float ps = 0.0f;
#pragma unroll
                    for (int j = 0; j < 8; j++) {
                        S[mi][j][gg * 2] = ex2(S[mi][j][gg * 2] - mcur);
                        S[mi][j][gg * 2 + 1] = ex2(S[mi][j][gg * 2 + 1] - mcur);
                        ps += S[mi][j][gg * 2] + S[mi][j][gg * 2 + 1];
                    }
                    ps += __shfl_xor_sync(0xffffffffu, ps, 1);
                    ps += __shfl_xor_sync(0xffffffffu, ps, 2);
                    lrow[mi][gg] += ps;
                }

            // ---- O += P V : C-frag pairs pack directly into fp16 A-frags ----
#pragma unroll
            for (int kc = 0; kc < 4; kc++) {
                uint32_t bV[4][4];
#pragma unroll
                for (int nj = 0; nj < 4; nj++)
                    ldsm4(bV[nj],
                          vb + sw128((16 * nj + b_row) * 128 + kc * 32 + b_coff));
#pragma unroll
                for (int mi = 0; mi < 2; mi++) {
                    uint32_t aP[4];
                    aP[0] = pack2h(S[mi][2 * kc][0], S[mi][2 * kc][1]);
                    aP[1] = pack2h(S[mi][2 * kc][2], S[mi][2 * kc][3]);
                    aP[2] = pack2h(S[mi][2 * kc + 1][0], S[mi][2 * kc + 1][1]);
                    aP[3] = pack2h(S[mi][2 * kc + 1][2], S[mi][2 * kc + 1][3]);
#pragma unroll
                    for (int oct = 0; oct < 8; oct++) {
                        const int j = oct >> 1, r = (oct & 1) * 2;
                        mma_f16(Oa[mi][oct], aP, bV[j][r], bV[j][r + 1]);
                    }
                }
            }
        }
        __syncthreads();
    }

    // ---- epilogue: normalize, fp16-pack, write [b,t,D] ----
    const int b = bh >> 4, hh = bh & 15;
#pragma unroll
    for (int mi = 0; mi < 2; mi++) {
        const float inv0 = 1.0f / lrow[mi][0];
        const float inv1 = 1.0f / lrow[mi][1];
        const int tq0 = qt * 256 + 32 * wid + 16 * mi + g;
#pragma unroll
        for (int oct = 0; oct < 8; oct++) {
            const int d = hh * 64 + 8 * oct + 2 * t;
            *(uint32_t*)&O[((size_t)b * NT + tq0) * ND + d] =
                pack2h(Oa[mi][oct][0] * inv0, Oa[mi][oct][1] * inv0);
            *(uint32_t*)&O[((size_t)b * NT + tq0 + 8) * ND + d] =
                pack2h(Oa[mi][oct][2] * inv1, Oa[mi][oct][3] * inv1);
        }
    }
}

// ---------------------------------------------------------------------------
// Inputs (metadata order): x, mask, Wq, bq, Wk, Wv, bv, Wo, bo
// ---------------------------------------------------------------------------
extern "C" void kernel_launch(void* const* d_in, const int* in_sizes, int n_in,
                              void* d_out, int out_size)
{
    const float* x  = (const float*)d_in[0];
    const float* Wq = (const float*)d_in[2];
    const float* bq = (const float*)d_in[3];
    const float* Wk = (const float*)d_in[4];
    const float* Wv = (const float*)d_in[5];
    const float* bv = (const float*)d_in[6];
    const float* Wo = (const float*)d_in[7];
    const float* bo = (const float*)d_in[8];
    float* out = (float*)d_out;

    __half *xh, *wqh, *wkh, *wvh, *woh, *qp, *kp, *vtp, *ohp;
    cudaGetSymbolAddress((void**)&xh, g_xh);
    cudaGetSymbolAddress((void**)&wqh, g_wqh);
    cudaGetSymbolAddress((void**)&wkh, g_wkh);
    cudaGetSymbolAddress((void**)&wvh, g_wvh);
    cudaGetSymbolAddress((void**)&woh, g_woh);
    cudaGetSymbolAddress((void**)&qp, g_q);
    cudaGetSymbolAddress((void**)&kp, g_k);
    cudaGetSymbolAddress((void**)&vtp, g_vt);
    cudaGetSymbolAddress((void**)&ohp, g_oh);

    cudaFuncSetAttribute(gemm_f16<0>,
                         cudaFuncAttributeMaxDynamicSharedMemorySize, 73728);
    cudaFuncSetAttribute(gemm_f16<1>,
                         cudaFuncAttributeMaxDynamicSharedMemorySize, 73728);
    cudaFuncSetAttribute(attn_f16,
                         cudaFuncAttributeMaxDynamicSharedMemorySize, 65536);

    const int M = NB * NT;                 // 8192
    const int xn4 = M * ND / 4;            // 2M

    toh_kernel<<<(xn4 + 255) / 256, 256>>>(x, xh, xn4);
    toh4_kernel<<<4096, 256>>>(Wq, Wk, Wv, Wo, wqh, wkh, wvh, woh);

    // fused QKV projection: N = 3072, region selected per block
    gemm_f16<1><<<dim3(3 * ND / 128, M / 256), 256, 73728>>>(
        xh, wqh, wkh, wvh, bq, bv, nullptr, nullptr, qp, kp, vtp);

    attn_f16<<<dim3(NT / 256, NB * NH), 256, 65536>>>(qp, kp, vtp, ohp);

    // output projection
    gemm_f16<0><<<dim3(ND / 128, M / 256), 256, 73728>>>(
        ohp, woh, nullptr, nullptr, nullptr, nullptr, bo, out,
        nullptr, nullptr, nullptr);
}

// round 16
// speedup vs baseline: 1.1156x; 1.1156x over previous
#include <cuda_runtime.h>
#include <cuda_fp16.h>
#include <cstdint>

#define NB 8
#define NT 1024
#define ND 1024
#define NH 16
#define HD 64
// hd^-0.5 * log2(e), folded into Q projection output (exp2-domain softmax)
#define QSCALE 0.1803368801111243f

// ---------------- scratch (device globals; no allocation allowed) ----------
__device__ __half g_xh[NB * NT * ND];
__device__ __half g_wqh[ND * ND], g_wkh[ND * ND], g_wvh[ND * ND], g_woh[ND * ND];
__device__ __half g_q[NB * NH * NT * HD], g_k[NB * NH * NT * HD];
__device__ __half g_vt[NB * NH * HD * NT];         // [b,h,d,t]
__device__ __half g_oh[NB * NT * ND];

// ---------------- helpers ---------------------------------------------------
__device__ __forceinline__ uint32_t smem_to_u32(const void* p) {
    uint32_t a;
    asm("{ .reg .u64 t; cvta.to.shared.u64 t, %1; cvt.u32.u64 %0, t; }"
        : "=r"(a) : "l"(p));
    return a;
}
__device__ __forceinline__ void ldsm4(uint32_t* r, uint32_t addr) {
    asm volatile("ldmatrix.sync.aligned.m8n8.x4.shared.b16 {%0,%1,%2,%3}, [%4];"
                 : "=r"(r[0]), "=r"(r[1]), "=r"(r[2]), "=r"(r[3]) : "r"(addr));
}
__device__ __forceinline__ void mma_f16(float* d, const uint32_t* a,
                                        uint32_t b0, uint32_t b1) {
    asm volatile(
        "mma.sync.aligned.m16n8k16.row.col.f32.f16.f16.f32 "
        "{%0,%1,%2,%3}, {%4,%5,%6,%7}, {%8,%9}, {%0,%1,%2,%3};"
        : "+f"(d[0]), "+f"(d[1]), "+f"(d[2]), "+f"(d[3])
        : "r"(a[0]), "r"(a[1]), "r"(a[2]), "r"(a[3]), "r"(b0), "r"(b1));
}
__device__ __forceinline__ void cpa16(uint32_t dst, const void* gsrc) {
    asm volatile("cp.async.cg.shared.global [%0], [%1], 16;"
                 :: "r"(dst), "l"(__cvta_generic_to_global(gsrc)) : "memory");
}
__device__ __forceinline__ uint32_t sw128(uint32_t off) {
    return off ^ ((off >> 3) & 0x70);
}
__device__ __forceinline__ uint32_t pack2h(float a, float b) {
    __half2 h = __floats2half2_rn(a, b);
    return *reinterpret_cast<uint32_t*>(&h);
}
__device__ __forceinline__ float ex2(float x) {
    float r;
    asm("ex2.approx.f32 %0, %1;" : "=f"(r) : "f"(x));
    return r;
}

// ---------------- fp32 -> fp16 conversion ------------------------------------
__global__ __launch_bounds__(256) void toh_kernel(
    const float* __restrict__ src, __half* __restrict__ dst, int n4)
{
    int i = blockIdx.x * 256 + threadIdx.x;
    if (i >= n4) return;
    float4 v = ((const float4*)src)[i];
    uint2 o;
    o.x = pack2h(v.x, v.y);
    o.y = pack2h(v.z, v.w);
    ((uint2*)dst)[i] = o;
}
// all 4 weight matrices in one launch; per-weight n4 = 2^18
__global__ __launch_bounds__(256) void toh4_kernel(
    const float* __restrict__ s0, const float* __restrict__ s1,
    const float* __restrict__ s2, const float* __restrict__ s3,
    __half* __restrict__ d0, __half* __restrict__ d1,
    __half* __restrict__ d2, __half* __restrict__ d3)
{
    const int i = blockIdx.x * 256 + threadIdx.x;
    const int w = i >> 18;
    const int j = i & 0x3FFFF;
    const float* src = (w == 0) ? s0 : (w == 1) ? s1 : (w == 2) ? s2 : s3;
    __half* dst = (w == 0) ? d0 : (w == 1) ? d1 : (w == 2) ? d2 : d3;
    float4 v = ((const float4*)src)[j];
    uint2 o;
    o.x = pack2h(v.x, v.y);
    o.y = pack2h(v.z, v.w);
    ((uint2*)dst)[j] = o;
}

// ---------------- fp16 single-pass GEMM --------------------------------------
// C[m,n] = sum_k A[m,k]*W[n,k]; CTA 128x128, 8 warps (2m x 4n), warp 64x32,
// k-step 16, 2-stage cp.async pipeline, rows padded to 48B.
// ~110 regs/thread + 24KB smem -> 2 CTAs/SM (the R4 occupancy shape).
// MODE 0: output GEMM -> fp32 [M,ND] + bias_o.
// MODE 1: fused QKV over N=3072; region 0=Q(bias+QSCALE), 1=K, 2=V([b,h,d,t]).
template <int MODE>
__global__ __launch_bounds__(256, 2) void gemm_f16(
    const __half* __restrict__ A,
    const __half* __restrict__ W0, const __half* __restrict__ W1,
    const __half* __restrict__ W2,
    const float* __restrict__ bias_q, const float* __restrict__ bias_v,
    const float* __restrict__ bias_o, float* __restrict__ Cf,
    __half* __restrict__ Qo, __half* __restrict__ Ko, __half* __restrict__ Vt)
{
    extern __shared__ __align__(16) char smemc[];
    const uint32_t sb = smem_to_u32(smemc);
    const int tid = threadIdx.x;
    const int wid = tid >> 5;
    const int lane = tid & 31;
    const int g = lane >> 2;
    const int t = lane & 3;
    const int m0 = (wid >> 2) * 64;       // 2 m-groups of 64
    const int n0 = (wid & 3) * 32;        // 4 n-groups of 32
    const int brow = blockIdx.y * 128;
    const int bcol = blockIdx.x * 128;

    int region = 0;
    const __half* B = W0;
    if (MODE == 1) {
        region = bcol >> 10;
        B = (region == 0) ? W0 : (region == 1 ? W1 : W2);
    }
    const int bn = bcol & 1023;

    float acc[4][4][4];
#pragma unroll
    for (int i = 0; i < 4; i++)
#pragma unroll
        for (int j = 0; j < 4; j++)
#pragma unroll
            for (int r = 0; r < 4; r++) acc[i][j][r] = 0.0f;

    // stage: A 128 rows x 48B @0; B 128 x 48B @6144; stage stride 12288
    auto load_stage = [&](int s, int kt) {
#pragma unroll
        for (int i = 0; i < 2; i++) {
            const int c = i * 256 + tid;          // 512 chunks of 16B
            const int tile = c >> 8;              // 0:A 1:B
            const int w = c & 255;
            const int row = w >> 1, ch = w & 1;
            const uint32_t dst = sb + s * 12288 + tile * 6144 + row * 48 + ch * 16;
            const __half* src = (tile ? B + (size_t)(bn + row) * ND
                                      : A + (size_t)(brow + row) * ND)
                                + kt * 16 + ch * 8;
            cpa16(dst, src);
        }
        asm volatile("cp.async.commit_group;" ::: "memory");
    };

    load_stage(0, 0);

    const uint32_t a_row = lane & 15;
    const uint32_t a_coff = (lane >> 4) << 4;
    const uint32_t b_row = (lane & 7) + (((lane >> 4) & 1) << 3);
    const uint32_t b_coff = ((lane >> 3) & 1) << 4;

    for (int kt = 0; kt < 64; kt++) {
        const int s = kt & 1;
        if (kt + 1 < 64) {
            load_stage(s ^ 1, kt + 1);
            asm volatile("cp.async.wait_group 1;" ::: "memory");
        } else {
            asm volatile("cp.async.wait_group 0;" ::: "memory");
        }
        __syncthreads();

        const uint32_t base = sb + s * 12288;
        uint32_t a[4][4], b[2][4];
#pragma unroll
        for (int mi = 0; mi < 4; mi++)
            ldsm4(a[mi], base + (m0 + 16 * mi + a_row) * 48 + a_coff);
#pragma unroll
        for (int nj = 0; nj < 2; nj++)
            ldsm4(b[nj], base + 6144 + (n0 + 16 * nj + b_row) * 48 + b_coff);
#pragma unroll
        for (int mi = 0; mi < 4; mi++)
#pragma unroll
            for (int ni = 0; ni < 4; ni++) {
                const int j = ni >> 1, r = (ni & 1) * 2;
                mma_f16(acc[mi][ni], a[mi], b[j][r], b[j][r + 1]);
            }
        __syncthreads();
    }

#pragma unroll
    for (int mi = 0; mi < 4; mi++) {
#pragma unroll
        for (int ni = 0; ni < 4; ni++) {
            const int mA = brow + m0 + 16 * mi + g;   // mA+8 stays in-batch
            const int c = n0 + 8 * ni + 2 * t;
            float2 v0, v1;
            v0.x = acc[mi][ni][0]; v0.y = acc[mi][ni][1];
            v1.x = acc[mi][ni][2]; v1.y = acc[mi][ni][3];
            if (MODE == 0) {
                const int n = bcol + c;
                const float2 bv = *(const float2*)(bias_o + n);
                v0.x += bv.x; v0.y += bv.y;
                v1.x += bv.x; v1.y += bv.y;
                *(float2*)&Cf[(size_t)mA * ND + n] = v0;
                *(float2*)&Cf[(size_t)(mA + 8) * ND + n] = v1;
            } else {
                const int nn = bn + c;
                const int hh = nn >> 6, d = nn & 63;
                const int b0_ = mA >> 10, t0 = mA & 1023;
                if (region == 0) {
                    const float2 bv = *(const float2*)(bias_q + nn);
                    v0.x = (v0.x + bv.x) * QSCALE; v0.y = (v0.y + bv.y) * QSCALE;
                    v1.x = (v1.x + bv.x) * QSCALE; v1.y = (v1.y + bv.y) * QSCALE;
                    const size_t i0 = (((size_t)(b0_ * NH + hh) * NT + t0) << 6) + d;
                    *(uint32_t*)&Qo[i0] = pack2h(v0.x, v0.y);
                    *(uint32_t*)&Qo[i0 + (8 << 6)] = pack2h(v1.x, v1.y);
                } else if (region == 1) {
                    const size_t i0 = (((size_t)(b0_ * NH + hh) * NT + t0) << 6) + d;
                    *(uint32_t*)&Ko[i0] = pack2h(v0.x, v0.y);
                    *(uint32_t*)&Ko[i0 + (8 << 6)] = pack2h(v1.x, v1.y);
                } else {
                    const float2 bv = *(const float2*)(bias_v + nn);
                    v0.x += bv.x; v0.y += bv.y;
                    v1.x += bv.x; v1.y += bv.y;
                    const size_t vbase = ((size_t)(b0_ * NH + hh) * HD + d) * NT;
                    Vt[vbase + t0] = __float2half_rn(v0.x);
                    Vt[vbase + NT + t0] = __float2half_rn(v0.y);
                    Vt[vbase + t0 + 8] = __float2half_rn(v1.x);
                    Vt[vbase + NT + t0 + 8] = __float2half_rn(v1.y);
                }
            }
        }
    }
}

// ---------------- fp16 causal flash attention (R13 semantics) ----------------
// Block: 256 queries x one (b,h); 8 warps x 32 q rows. Q frags persistent in
// registers; K/V in 64-key sw128 tiles, double-buffered; fully masked diagonal
// tiles skipped per warp. Scores in exp2 domain (QSCALE folded into Q).
// smem: Q [0,32768); stage s: K @32768+s*16384, V @+8192. Total 65536 B.
__global__ __launch_bounds__(256, 1) void attn_f16(
    const __half* __restrict__ Q, const __half* __restrict__ K,
    const __half* __restrict__ Vt, __half* __restrict__ O)
{
    extern __shared__ __align__(16) char smemc[];
    const uint32_t sb = smem_to_u32(smemc);
    const int qt = gridDim.x - 1 - blockIdx.x;   // heavy blocks first
    const int bh = blockIdx.y;
    const int tid = threadIdx.x;
    const int wid = tid >> 5;
    const int lane = tid & 31;
    const int g = lane >> 2;
    const int t = lane & 3;

    const size_t off = (size_t)bh * NT * HD;     // same count for Vt [b,h,d,t]

    auto load_tile = [&](int kt, int s) {
        const uint32_t kb = sb + 32768 + s * 16384;
        const uint32_t vb = kb + 8192;
#pragma unroll
        for (int i = 0; i < 4; i++) {
            const int c = i * 256 + tid;          // 1024 chunks
            const int tile = c >> 9;              // 0:K 1:V
            const int w = c & 511;
            const int row = w >> 3;
            const int ch = w & 7;
            if (tile == 0)
                cpa16(kb + sw128(row * 128 + ch * 16),
                      K + off + (size_t)(kt * 64 + row) * HD + ch * 8);
            else
                cpa16(vb + sw128(row * 128 + ch * 16),
                      Vt + off + (size_t)row * NT + kt * 64 + ch * 8);
        }
        asm volatile("cp.async.commit_group;" ::: "memory");
    };

    // stage Q (256 x 64 halves): 2048 chunks
#pragma unroll
    for (int i = 0; i < 8; i++) {
        const int c = i * 256 + tid;
        const int row = c >> 3;
        const int ch = c & 7;
        cpa16(sb + sw128(row * 128 + ch * 16),
              Q + off + (size_t)(qt * 256 + row) * HD + ch * 8);
    }
    asm volatile("cp.async.commit_group;" ::: "memory");

    const int nkt = 4 * qt + 4;
    load_tile(0, 0);
    asm volatile("cp.async.wait_group 1;" ::: "memory");   // Q staged
    __syncthreads();

    const uint32_t a_row = lane & 15;
    const uint32_t a_coff = (lane >> 4) << 4;
    const uint32_t b_row = (lane & 7) + (((lane >> 4) & 1) << 3);
    const uint32_t b_coff = ((lane >> 3) & 1) << 4;

    // persistent Q fragments: 2 m-tiles x 4 k-chunks
    uint32_t qf[2][4][4];
#pragma unroll
    for (int mi = 0; mi < 2; mi++)
#pragma unroll
        for (int kc = 0; kc < 4; kc++)
            ldsm4(qf[mi][kc],
                  sb + sw128((32 * wid + 16 * mi + a_row) * 128 + kc * 32 + a_coff));

    float Oa[2][8][4];
#pragma unroll
    for (int mi = 0; mi < 2; mi++)
#pragma unroll
        for (int j = 0; j < 8; j++)
#pragma unroll
            for (int r = 0; r < 4; r++) Oa[mi][j][r] = 0.0f;
    float mrow[2][2] = {{-3.0e38f, -3.0e38f}, {-3.0e38f, -3.0e38f}};
    float lrow[2][2] = {{0.0f, 0.0f}, {0.0f, 0.0f}};

    for (int kt = 0; kt < nkt; kt++) {
        const int s = kt & 1;
        if (kt + 1 < nkt) {
            load_tile(kt + 1, s ^ 1);
            asm volatile("cp.async.wait_group 1;" ::: "memory");
        } else {
            asm volatile("cp.async.wait_group 0;" ::: "memory");
        }
        __syncthreads();

        if (kt * 64 <= qt * 256 + 32 * wid + 31) {   // warp-uniform causal skip
            const uint32_t kb = sb + 32768 + s * 16384;
            const uint32_t vb = kb + 8192;

            // ---- S = Q K^T ----
            float S[2][8][4];
#pragma unroll
            for (int mi = 0; mi < 2; mi++)
#pragma unroll
                for (int j = 0; j < 8; j++)
#pragma unroll
                    for (int r = 0; r < 4; r++) S[mi][j][r] = 0.0f;

#pragma unroll
            for (int kc = 0; kc < 4; kc++) {
                uint32_t bK[4][4];
#pragma unroll
                for (int nj = 0; nj < 4; nj++)
                    ldsm4(bK[nj],
                          kb + sw128((16 * nj + b_row) * 128 + kc * 32 + b_coff));
#pragma unroll
                for (int oct = 0; oct < 8; oct++) {
                    const int j = oct >> 1, r = (oct & 1) * 2;
                    mma_f16(S[0][oct], qf[0][kc], bK[j][r], bK[j][r + 1]);
                    mma_f16(S[1][oct], qf[1][kc], bK[j][r], bK[j][r + 1]);
                }
            }

            // ---- causal mask (diagonal region only) ----
            if (kt >= 4 * qt) {
#pragma unroll
                for (int mi = 0; mi < 2; mi++)
#pragma unroll
                    for (int j = 0; j < 8; j++)
#pragma unroll
                        for (int r = 0; r < 4; r++) {
                            const int rq = qt * 256 + 32 * wid + 16 * mi + g
                                         + 8 * (r >> 1);
                            const int ck = kt * 64 + 8 * j + 2 * t + (r & 1);
                            if (ck > rq) S[mi][j][r] = -1.0e30f;
                        }
            }

            // ---- online softmax (exp2 domain) ----
#pragma unroll
            for (int mi = 0; mi < 2; mi++)
#pragma unroll
                for (int gg = 0; gg < 2; gg++) {
                    float mx = -3.0e38f;
#pragma unroll
                    for (int j = 0; j < 8; j++) {
                        mx = fmaxf(mx, S[mi][j][gg * 2]);
                        mx = fmaxf(mx, S[mi][j][gg * 2 + 1]);
                    }
                    mx = fmaxf(mx, __shfl_xor_sync(0xffffffffu, mx, 1));
                    mx = fmaxf(mx, __shfl_xor_sync(0xffffffffu, mx, 2));
                    const float mnew = fmaxf(mrow[mi][gg], mx);
                    const float corr = ex2(mrow[mi][gg] - mnew);
                    mrow[mi][gg] = mnew;
                    float ps = 0.0f;
#pragma unroll
                    for (int j = 0; j < 8; j++) {
                        S[mi][j][gg * 2] = ex2(S[mi][j][gg * 2] - mnew);
                        S[mi][j][gg * 2 + 1] = ex2(S[mi][j][gg * 2 + 1] - mnew);
                        ps += S[mi][j][gg * 2] + S[mi][j][gg * 2 + 1];
                    }
                    ps += __shfl_xor_sync(0xffffffffu, ps, 1);
                    ps += __shfl_xor_sync(0xffffffffu, ps, 2);
                    lrow[mi][gg] = lrow[mi][gg] * corr + ps;
#pragma unroll
                    for (int j = 0; j < 8; j++) {
                        Oa[mi][j][gg * 2] *= corr;
                        Oa[mi][j][gg * 2 + 1] *= corr;
                    }
                }

            // ---- O += P V : C-frag pairs pack directly into fp16 A-frags ----
#pragma unroll
            for (int kc = 0; kc < 4; kc++) {
                uint32_t bV[4][4];
#pragma unroll
                for (int nj = 0; nj < 4; nj++)
                    ldsm4(bV[nj],
                          vb + sw128((16 * nj + b_row) * 128 + kc * 32 + b_coff));
#pragma unroll
                for (int mi = 0; mi < 2; mi++) {
                    uint32_t aP[4];
                    aP[0] = pack2h(S[mi][2 * kc][0], S[mi][2 * kc][1]);
                    aP[1] = pack2h(S[mi][2 * kc][2], S[mi][2 * kc][3]);
                    aP[2] = pack2h(S[mi][2 * kc + 1][0], S[mi][2 * kc + 1][1]);
                    aP[3] = pack2h(S[mi][2 * kc + 1][2], S[mi][2 * kc + 1][3]);
#pragma unroll
                    for (int oct = 0; oct < 8; oct++) {
                        const int j = oct >> 1, r = (oct & 1) * 2;
                        mma_f16(Oa[mi][oct], aP, bV[j][r], bV[j][r + 1]);
                    }
                }
            }
        }
        __syncthreads();
    }

    // ---- epilogue: normalize, fp16-pack, write [b,t,D] ----
    const int b = bh >> 4, hh = bh & 15;
#pragma unroll
    for (int mi = 0; mi < 2; mi++) {
        const float inv0 = 1.0f / lrow[mi][0];
        const float inv1 = 1.0f / lrow[mi][1];
        const int tq0 = qt * 256 + 32 * wid + 16 * mi + g;
#pragma unroll
        for (int oct = 0; oct < 8; oct++) {
            const int d = hh * 64 + 8 * oct + 2 * t;
            *(uint32_t*)&O[((size_t)b * NT + tq0) * ND + d] =
                pack2h(Oa[mi][oct][0] * inv0, Oa[mi][oct][1] * inv0);
            *(uint32_t*)&O[((size_t)b * NT + tq0 + 8) * ND + d] =
                pack2h(Oa[mi][oct][2] * inv1, Oa[mi][oct][3] * inv1);
        }
    }
}

// ---------------------------------------------------------------------------
// Inputs (metadata order): x, mask, Wq, bq, Wk, Wv, bv, Wo, bo
// ---------------------------------------------------------------------------
extern "C" void kernel_launch(void* const* d_in, const int* in_sizes, int n_in,
                              void* d_out, int out_size)
{
    const float* x  = (const float*)d_in[0];
    const float* Wq = (const float*)d_in[2];
    const float* bq = (const float*)d_in[3];
    const float* Wk = (const float*)d_in[4];
    const float* Wv = (const float*)d_in[5];
    const float* bv = (const float*)d_in[6];
    const float* Wo = (const float*)d_in[7];
    const float* bo = (const float*)d_in[8];
    float* out = (float*)d_out;

    __half *xh, *wqh, *wkh, *wvh, *woh, *qp, *kp, *vtp, *ohp;
    cudaGetSymbolAddress((void**)&xh, g_xh);
    cudaGetSymbolAddress((void**)&wqh, g_wqh);
    cudaGetSymbolAddress((void**)&wkh, g_wkh);
    cudaGetSymbolAddress((void**)&wvh, g_wvh);
    cudaGetSymbolAddress((void**)&woh, g_woh);
    cudaGetSymbolAddress((void**)&qp, g_q);
    cudaGetSymbolAddress((void**)&kp, g_k);
    cudaGetSymbolAddress((void**)&vtp, g_vt);
    cudaGetSymbolAddress((void**)&ohp, g_oh);

    cudaFuncSetAttribute(gemm_f16<0>,
                         cudaFuncAttributeMaxDynamicSharedMemorySize, 24576);
    cudaFuncSetAttribute(gemm_f16<1>,
                         cudaFuncAttributeMaxDynamicSharedMemorySize, 24576);
    cudaFuncSetAttribute(attn_f16,
                         cudaFuncAttributeMaxDynamicSharedMemorySize, 65536);

    const int M = NB * NT;                 // 8192
    const int xn4 = M * ND / 4;            // 2M

    toh_kernel<<<(xn4 + 255) / 256, 256>>>(x, xh, xn4);
    toh4_kernel<<<4096, 256>>>(Wq, Wk, Wv, Wo, wqh, wkh, wvh, woh);

    // fused QKV projection: N = 3072, region selected per block
    gemm_f16<1><<<dim3(3 * ND / 128, M / 128), 256, 24576>>>(
        xh, wqh, wkh, wvh, bq, bv, nullptr, nullptr, qp, kp, vtp);

    attn_f16<<<dim3(NT / 256, NB * NH), 256, 65536>>>(qp, kp, vtp, ohp);

    // output projection
    gemm_f16<0><<<dim3(ND / 128, M / 128), 256, 24576>>>(
        ohp, woh, nullptr, nullptr, nullptr, nullptr, bo, out,
        nullptr, nullptr, nullptr);
}